// round 1
// baseline (speedup 1.0000x reference)
#include <cuda_runtime.h>
#include <cuda_fp16.h>
#include <stdint.h>

#define H      2048
#define FOURH  8192
#define TSEQ   2048
#define FUT    128
#define TOT    (TSEQ + FUT)
#define NB     148
#define NT     1024

#define GATE_STRIDE ((size_t)2048 * (size_t)H)   // halves between gate rows for same j

// ---------------- persistent device state (no allocations allowed) ----------------
__device__ __half g_w1 [(size_t)FOURH * H];   // w_hh1 fp16
__device__ __half g_w2i[(size_t)FOURH * H];   // w_ih2 fp16
__device__ __half g_w2h[(size_t)FOURH * H];   // w_hh2 fp16
__device__ float  g_b1[FOURH];                // b_ih1 + b_hh1
__device__ float  g_b2[FOURH];                // b_ih2 + b_hh2
__device__ float  g_h1[2][H];                 // double-buffered hidden states
__device__ float  g_h2[2][H];
__device__ float  g_part[NB];                 // per-block output partials
__device__ unsigned g_count;
__device__ unsigned g_sense;

// ---------------- prep: fp32 -> fp16 weights, bias sums, barrier reset ----------------
__global__ void prep_kernel(const float* __restrict__ w_hh1,
                            const float* __restrict__ w_ih2,
                            const float* __restrict__ w_hh2,
                            const float* __restrict__ b_ih1,
                            const float* __restrict__ b_hh1,
                            const float* __restrict__ b_ih2,
                            const float* __restrict__ b_hh2)
{
    const size_t n = (size_t)FOURH * H;
    const size_t stride = (size_t)gridDim.x * blockDim.x;
    size_t i0 = (size_t)blockIdx.x * blockDim.x + threadIdx.x;
    for (size_t k = i0; k < n; k += stride) {
        g_w1 [k] = __float2half_rn(w_hh1[k]);
        g_w2i[k] = __float2half_rn(w_ih2[k]);
        g_w2h[k] = __float2half_rn(w_hh2[k]);
    }
    if (i0 < FOURH) {
        g_b1[i0] = b_ih1[i0] + b_hh1[i0];
        g_b2[i0] = b_ih2[i0] + b_hh2[i0];
    }
    if (i0 == 0) { g_count = 0u; g_sense = 0u; }
}

// ---------------- grid-wide barrier (148 co-resident CTAs, sense via monotonic phase) ----
__device__ __forceinline__ void grid_sync(unsigned* phase)
{
    __syncthreads();
    if (threadIdx.x == 0) {
        const unsigned target = ++(*phase);
        __threadfence();
        if (atomicAdd(&g_count, 1u) == (unsigned)(NB - 1)) {
            g_count = 0u;
            __threadfence();
            atomicExch(&g_sense, target);
        } else {
            while (*((volatile unsigned*)&g_sense) < target) { }
            __threadfence();
        }
    }
    __syncthreads();
}

__device__ __forceinline__ float sigf(float x) { return 1.0f / (1.0f + expf(-x)); }

// dot over 1024 elements for all 4 gate rows of one hidden index j.
// w: base of row (gate 0) at the chosen k-half; hs: shared-memory h at same k-half.
__device__ __forceinline__ void dot4(const __half* __restrict__ w,
                                     const float* hs, int lane, float acc[4])
{
    acc[0] = acc[1] = acc[2] = acc[3] = 0.0f;
    #pragma unroll
    for (int m = 0; m < 4; ++m) {
        const int base = m * 256 + lane * 8;
        const float4 ha = *reinterpret_cast<const float4*>(hs + base);
        const float4 hb = *reinterpret_cast<const float4*>(hs + base + 4);
        #pragma unroll
        for (int g = 0; g < 4; ++g) {
            const uint4 wv = *reinterpret_cast<const uint4*>(w + (size_t)g * GATE_STRIDE + base);
            const float2 f0 = __half22float2(*reinterpret_cast<const __half2*>(&wv.x));
            const float2 f1 = __half22float2(*reinterpret_cast<const __half2*>(&wv.y));
            const float2 f2 = __half22float2(*reinterpret_cast<const __half2*>(&wv.z));
            const float2 f3 = __half22float2(*reinterpret_cast<const __half2*>(&wv.w));
            float a = acc[g];
            a = fmaf(f0.x, ha.x, a); a = fmaf(f0.y, ha.y, a);
            a = fmaf(f1.x, ha.z, a); a = fmaf(f1.y, ha.w, a);
            a = fmaf(f2.x, hb.x, a); a = fmaf(f2.y, hb.y, a);
            a = fmaf(f3.x, hb.z, a); a = fmaf(f3.y, hb.w, a);
            acc[g] = a;
        }
    }
}

__device__ __forceinline__ void reduce4(float acc[4])
{
    #pragma unroll
    for (int g = 0; g < 4; ++g) {
        #pragma unroll
        for (int o = 16; o > 0; o >>= 1)
            acc[g] += __shfl_xor_sync(0xffffffffu, acc[g], o);
    }
}

// ---------------- main persistent kernel ----------------
__global__ void __launch_bounds__(NT, 1)
lstm_main(const float* __restrict__ input,
          const float* __restrict__ w_ih1,
          const float* __restrict__ w_lin,
          const float* __restrict__ b_lin,
          float* __restrict__ out)
{
    const int b    = blockIdx.x;
    const int tid  = threadIdx.x;
    const int warp = tid >> 5;
    const int lane = tid & 31;
    const int nI   = (H - b + NB - 1) / NB;   // 14 for b<124, else 13

    __shared__ float s_h[2 * H];        // staged hidden vectors (16 KB)
    __shared__ float s_g1[14][4][2];
    __shared__ float s_g2[14][4][4];
    __shared__ float s_c1[14], s_c2[14], s_o[14];
    __shared__ float s_bcast;

    unsigned phase = 0;

    // init owned state (both parities) to zero
    if (tid < nI) {
        const int j = b + tid * NB;
        s_c1[tid] = 0.0f; s_c2[tid] = 0.0f;
        g_h1[0][j] = 0.0f; g_h1[1][j] = 0.0f;
        g_h2[0][j] = 0.0f; g_h2[1][j] = 0.0f;
    }
    grid_sync(&phase);

    float cur_out = 0.0f;
    const float blin = __ldg(b_lin);

    for (int t = 0; t < TOT; ++t) {
        const int cur  = t & 1;
        const int prev = cur ^ 1;
        const float x = (t < TSEQ) ? __ldg(input + t) : cur_out;

        // ---- stage h1(prev) into smem (L2-coherent loads; L1 may be stale) ----
        #pragma unroll
        for (int k = tid; k < H; k += NT) s_h[k] = __ldcg(&g_h1[prev][k]);
        __syncthreads();

        // ---- layer 1 dots: task = (i, k-half) ----
        for (int task = warp; task < nI * 2; task += 32) {
            const int i  = task >> 1;
            const int kh = task & 1;
            const int j  = b + i * NB;
            float acc[4];
            dot4(g_w1 + (size_t)j * H + kh * (H / 2), s_h + kh * (H / 2), lane, acc);
            reduce4(acc);
            if (lane == 0) {
                s_g1[i][0][kh] = acc[0]; s_g1[i][1][kh] = acc[1];
                s_g1[i][2][kh] = acc[2]; s_g1[i][3][kh] = acc[3];
            }
        }
        __syncthreads();

        // ---- layer 1 elementwise ----
        if (tid < nI) {
            const int j = b + tid * NB;
            const float gi = s_g1[tid][0][0] + s_g1[tid][0][1] + g_b1[j]        + __ldg(w_ih1 + j)        * x;
            const float gf = s_g1[tid][1][0] + s_g1[tid][1][1] + g_b1[j + 2048] + __ldg(w_ih1 + j + 2048) * x;
            const float gg = s_g1[tid][2][0] + s_g1[tid][2][1] + g_b1[j + 4096] + __ldg(w_ih1 + j + 4096) * x;
            const float go = s_g1[tid][3][0] + s_g1[tid][3][1] + g_b1[j + 6144] + __ldg(w_ih1 + j + 6144) * x;
            const float c  = sigf(gf) * s_c1[tid] + sigf(gi) * tanhf(gg);
            s_c1[tid] = c;
            g_h1[cur][j] = sigf(go) * tanhf(c);
        }
        grid_sync(&phase);

        // ---- stage h1(cur) and h2(prev) ----
        #pragma unroll
        for (int k = tid; k < H; k += NT) s_h[k]     = __ldcg(&g_h1[cur][k]);
        #pragma unroll
        for (int k = tid; k < H; k += NT) s_h[H + k] = __ldcg(&g_h2[prev][k]);
        __syncthreads();

        // ---- layer 2 dots: task = (i, src, k-half) ----
        for (int task = warp; task < nI * 4; task += 32) {
            const int i   = task >> 2;
            const int sub = task & 3;
            const int src = sub >> 1;      // 0: w_ih2 vs h1, 1: w_hh2 vs h2
            const int kh  = sub & 1;
            const int j   = b + i * NB;
            const __half* w = (src ? g_w2h : g_w2i) + (size_t)j * H + kh * (H / 2);
            const float*  hv = s_h + src * H + kh * (H / 2);
            float acc[4];
            dot4(w, hv, lane, acc);
            reduce4(acc);
            if (lane == 0) {
                s_g2[i][0][sub] = acc[0]; s_g2[i][1][sub] = acc[1];
                s_g2[i][2][sub] = acc[2]; s_g2[i][3][sub] = acc[3];
            }
        }
        __syncthreads();

        // ---- layer 2 elementwise + output partial ----
        if (tid < nI) {
            const int j = b + tid * NB;
            const float gi = s_g2[tid][0][0] + s_g2[tid][0][1] + s_g2[tid][0][2] + s_g2[tid][0][3] + g_b2[j];
            const float gf = s_g2[tid][1][0] + s_g2[tid][1][1] + s_g2[tid][1][2] + s_g2[tid][1][3] + g_b2[j + 2048];
            const float gg = s_g2[tid][2][0] + s_g2[tid][2][1] + s_g2[tid][2][2] + s_g2[tid][2][3] + g_b2[j + 4096];
            const float go = s_g2[tid][3][0] + s_g2[tid][3][1] + s_g2[tid][3][2] + s_g2[tid][3][3] + g_b2[j + 6144];
            const float c  = sigf(gf) * s_c2[tid] + sigf(gi) * tanhf(gg);
            s_c2[tid] = c;
            const float h = sigf(go) * tanhf(c);
            g_h2[cur][j] = h;
            s_o[tid] = h * __ldg(w_lin + j);
        }
        __syncthreads();
        if (tid == 0) {
            float s = 0.0f;
            for (int i = 0; i < nI; ++i) s += s_o[i];
            g_part[b] = s;
        }
        grid_sync(&phase);

        // ---- every block redundantly (deterministically) reduces the scalar output ----
        if (warp == 0) {
            float s = 0.0f;
            for (int p = lane; p < NB; p += 32) s += __ldcg(&g_part[p]);
            #pragma unroll
            for (int o = 16; o > 0; o >>= 1) s += __shfl_xor_sync(0xffffffffu, s, o);
            if (lane == 0) s_bcast = s + blin;
        }
        __syncthreads();
        cur_out = s_bcast;
        if (b == 0 && tid == 0) out[t] = cur_out;
    }
}

// ---------------- launch ----------------
extern "C" void kernel_launch(void* const* d_in, const int* in_sizes, int n_in,
                              void* d_out, int out_size)
{
    const float* input = (const float*)d_in[0];
    const float* w_ih1 = (const float*)d_in[1];
    const float* w_hh1 = (const float*)d_in[2];
    const float* b_ih1 = (const float*)d_in[3];
    const float* b_hh1 = (const float*)d_in[4];
    const float* w_ih2 = (const float*)d_in[5];
    const float* w_hh2 = (const float*)d_in[6];
    const float* b_ih2 = (const float*)d_in[7];
    const float* b_hh2 = (const float*)d_in[8];
    const float* w_lin = (const float*)d_in[9];
    const float* b_lin = (const float*)d_in[10];
    float* out = (float*)d_out;

    prep_kernel<<<1024, 256>>>(w_hh1, w_ih2, w_hh2, b_ih1, b_hh1, b_ih2, b_hh2);
    lstm_main<<<NB, NT>>>(input, w_ih1, w_lin, b_lin, out);
}